// round 6
// baseline (speedup 1.0000x reference)
#include <cuda_runtime.h>
#include <cuda_bf16.h>
#include <cstdint>

// ConvEmbedding: out[n,i] = normalize_row( sum_k w[i,k]*x[n,i+k] + b[i] )
// C = X(16384x2048) @ W_band(512x2048)^T, bf16 3-term split via mma.sync.
// R6: inner loop restructured to 8-reg A fragments (no spills at occ 2).

#define N_ROWS 16384
#define D_DIM  2048
#define E_DIM  512
#define K_DIM  1537

#define BM 128
#define BN 128
#define BK 32
#define PITCH 40                 // bf16 elems per smem row (80 B)
#define NITER 52                 // 1664 / 32, uniform for every E tile
#define THREADS 256

#define TILE_SMEM (BM * PITCH * 2)           // 10240 B per tile
#define STAGE_SMEM (4 * TILE_SMEM)           // Ahi, Alo, Bhi, Blo = 40960 B
#define SMEM_BYTES (2 * STAGE_SMEM)          // double buffered = 81920 B

// ---------------- scratch (device globals) ----------------------------------
__device__ __nv_bfloat16 g_Whi[(size_t)E_DIM * D_DIM];
__device__ __nv_bfloat16 g_Wlo[(size_t)E_DIM * D_DIM];

// ---------------- kernel 1: build banded W, split hi/lo ----------------------
__global__ void build_band_kernel(const float* __restrict__ w) {
    const int i = blockIdx.x;  // 0..511
    const float* wrow = w + (size_t)i * K_DIM;
    for (int c = threadIdx.x; c < D_DIM; c += blockDim.x) {
        const int k = c - i;
        const float val = (k >= 0 && k < K_DIM) ? wrow[k] : 0.0f;
        const __nv_bfloat16 hi = __float2bfloat16(val);
        g_Whi[(size_t)i * D_DIM + c] = hi;
        g_Wlo[(size_t)i * D_DIM + c] = __float2bfloat16(val - __bfloat162float(hi));
    }
}

// ---------------- mma helpers ------------------------------------------------
__device__ __forceinline__ void ldm_x4(uint32_t* r, uint32_t saddr) {
    asm volatile("ldmatrix.sync.aligned.m8n8.x4.shared.b16 {%0,%1,%2,%3}, [%4];"
                 : "=r"(r[0]), "=r"(r[1]), "=r"(r[2]), "=r"(r[3]) : "r"(saddr));
}
__device__ __forceinline__ void mma_bf16(float* d, const uint32_t* a, const uint32_t* b) {
    asm volatile(
        "mma.sync.aligned.m16n8k16.row.col.f32.bf16.bf16.f32 "
        "{%0,%1,%2,%3}, {%4,%5,%6,%7}, {%8,%9}, {%0,%1,%2,%3};"
        : "+f"(d[0]), "+f"(d[1]), "+f"(d[2]), "+f"(d[3])
        : "r"(a[0]), "r"(a[1]), "r"(a[2]), "r"(a[3]), "r"(b[0]), "r"(b[1]));
}
__device__ __forceinline__ void cp_async16(uint32_t saddr, const void* gaddr) {
    asm volatile("cp.async.cg.shared.global [%0], [%1], 16;" :: "r"(saddr), "l"(gaddr));
}

// Convert 8 fp32 -> packed hi (4 u32) and lo (4 u32)
__device__ __forceinline__ void split8(const float* v, uint32_t* hi, uint32_t* lo) {
    #pragma unroll
    for (int j = 0; j < 4; j++) {
        const float a = v[j * 2], b = v[j * 2 + 1];
        const __nv_bfloat162 h = __float22bfloat162_rn(make_float2(a, b));
        const float ra = a - __bfloat162float(h.x);
        const float rb = b - __bfloat162float(h.y);
        const __nv_bfloat162 l = __float22bfloat162_rn(make_float2(ra, rb));
        hi[j] = *reinterpret_cast<const uint32_t*>(&h);
        lo[j] = *reinterpret_cast<const uint32_t*>(&l);
    }
}

// ---------------- kernel 2: bf16-split GEMM ----------------------------------
// Warp layout: 2 warps along M (tile 64) x 4 warps along N (tile 32).
// A loaded as fp32 LDG (one stage ahead), split to bf16 hi/lo in regs, STS'd.
// Inner loop: b_hi/b_lo resident (16 regs), A fragments cycled through 8 regs.
__global__ __launch_bounds__(THREADS, 2)
void mma_gemm_kernel(const float* __restrict__ X, float* __restrict__ C) {
    extern __shared__ __align__(128) char smem[];
    const uint32_t sb = (uint32_t)__cvta_generic_to_shared(smem);

    const int tid  = threadIdx.x;
    const int lane = tid & 31;
    const int wid  = tid >> 5;
    const int wm   = wid & 1;          // 2 warps along M: rows wm*64
    const int wn   = wid >> 1;         // 4 warps along N: cols wn*32
    const int bx = blockIdx.x;         // E tile (0..3)
    const int by = blockIdx.y;         // batch tile (0..127)
    const int i0 = bx * BN;
    const int kStart = i0;

    // ---- A loader: thread handles row tid>>1, 16 consecutive cols
    const int arow = tid >> 1;
    const int acol = (tid & 1) * 16;
    const float* Ap = X + (size_t)(by * BM + arow) * D_DIM + acol;
    const uint32_t aSts = (uint32_t)(arow * PITCH + acol) * 2;  // byte off in tile

    // ---- B loader (cp.async): 4 chunks, tiles Bhi/Blo at slots 2,3
    const __nv_bfloat16* Bsrc[2] = { g_Whi + (size_t)i0 * D_DIM,
                                     g_Wlo + (size_t)i0 * D_DIM };
    int brow[4], bcol[4];
    #pragma unroll
    for (int i = 0; i < 4; i++) {
        const int v = ((i & 1) << 8) + tid;   // 0..511 within tile
        brow[i] = v >> 2;
        bcol[i] = (v & 3) * 8;
    }

    // fragment smem offsets (bytes, lane-dependent), relative to tile base
    const uint32_t aoff = ((uint32_t)((wm * 64 + (lane & 15)) * PITCH + (lane >> 4) * 8)) * 2;
    const uint32_t boff = ((uint32_t)((wn * 32 + (lane >> 4) * 8 + (lane & 7)) * PITCH
                                      + ((lane >> 3) & 1) * 8)) * 2;

    float acc[4][4][4];
    #pragma unroll
    for (int mt = 0; mt < 4; mt++)
        #pragma unroll
        for (int nt = 0; nt < 4; nt++)
            #pragma unroll
            for (int q = 0; q < 4; q++) acc[mt][nt][q] = 0.0f;

    float av[16];   // fp32 A prefetch (one stage ahead)

    // ---- prologue: stage 0
    {
        const int k0 = kStart;
        #pragma unroll
        for (int i = 0; i < 4; i++)
            cp_async16(sb + (2 + (i >> 1)) * TILE_SMEM + (brow[i] * PITCH + bcol[i]) * 2,
                       Bsrc[i >> 1] + (size_t)brow[i] * D_DIM + k0 + bcol[i]);
        asm volatile("cp.async.commit_group;" ::: "memory");

        #pragma unroll
        for (int q = 0; q < 4; q++)
            *reinterpret_cast<float4*>(&av[q * 4]) =
                *reinterpret_cast<const float4*>(Ap + k0 + q * 4);
        uint32_t hi[8], lo[8];
        split8(&av[0], &hi[0], &lo[0]);
        split8(&av[8], &hi[4], &lo[4]);
        *reinterpret_cast<uint4*>(smem + 0 * TILE_SMEM + aSts)      = *reinterpret_cast<uint4*>(&hi[0]);
        *reinterpret_cast<uint4*>(smem + 0 * TILE_SMEM + aSts + 16) = *reinterpret_cast<uint4*>(&hi[4]);
        *reinterpret_cast<uint4*>(smem + 1 * TILE_SMEM + aSts)      = *reinterpret_cast<uint4*>(&lo[0]);
        *reinterpret_cast<uint4*>(smem + 1 * TILE_SMEM + aSts + 16) = *reinterpret_cast<uint4*>(&lo[4]);
    }

    for (int it = 0; it < NITER; it++) {
        const int has_next = (it + 1 < NITER);
        if (has_next) {
            const int k0 = kStart + (it + 1) * BK;
            const uint32_t stg = sb + ((it + 1) & 1) * STAGE_SMEM;
            #pragma unroll
            for (int i = 0; i < 4; i++)
                cp_async16(stg + (2 + (i >> 1)) * TILE_SMEM + (brow[i] * PITCH + bcol[i]) * 2,
                           Bsrc[i >> 1] + (size_t)brow[i] * D_DIM + k0 + bcol[i]);
            asm volatile("cp.async.commit_group;" ::: "memory");
            #pragma unroll
            for (int q = 0; q < 4; q++)
                *reinterpret_cast<float4*>(&av[q * 4]) =
                    *reinterpret_cast<const float4*>(Ap + k0 + q * 4);
            asm volatile("cp.async.wait_group 1;" ::: "memory");
        } else {
            asm volatile("cp.async.wait_group 0;" ::: "memory");
        }
        __syncthreads();

        const uint32_t stg = sb + (it & 1) * STAGE_SMEM;
        const uint32_t sAhi = stg + 0 * TILE_SMEM + aoff;
        const uint32_t sAlo = stg + 1 * TILE_SMEM + aoff;
        const uint32_t sBhi = stg + 2 * TILE_SMEM + boff;
        const uint32_t sBlo = stg + 3 * TILE_SMEM + boff;

        #pragma unroll
        for (int k16 = 0; k16 < BK; k16 += 16) {
            const uint32_t ko = k16 * 2;  // byte offset in row
            uint32_t bhi[8], blo[8];

            #pragma unroll
            for (int bt = 0; bt < 2; bt++)
                ldm_x4(&bhi[bt * 4], sBhi + (uint32_t)(bt * 16 * PITCH) * 2 + ko);
            #pragma unroll
            for (int bt = 0; bt < 2; bt++)
                ldm_x4(&blo[bt * 4], sBlo + (uint32_t)(bt * 16 * PITCH) * 2 + ko);

            // process m-tiles in pairs: A fragments live in 8 regs only
            #pragma unroll
            for (int mp = 0; mp < 2; mp++) {
                uint32_t a[8];
                #pragma unroll
                for (int m2 = 0; m2 < 2; m2++)
                    ldm_x4(&a[m2 * 4], sAhi + (uint32_t)((mp * 2 + m2) * 16 * PITCH) * 2 + ko);
                // term 1: a_hi * b_hi
                #pragma unroll
                for (int m2 = 0; m2 < 2; m2++)
                    #pragma unroll
                    for (int nt = 0; nt < 4; nt++)
                        mma_bf16(acc[mp * 2 + m2][nt], &a[m2 * 4], &bhi[nt * 2]);
                // term 2: a_hi * b_lo
                #pragma unroll
                for (int m2 = 0; m2 < 2; m2++)
                    #pragma unroll
                    for (int nt = 0; nt < 4; nt++)
                        mma_bf16(acc[mp * 2 + m2][nt], &a[m2 * 4], &blo[nt * 2]);
                // term 3: a_lo * b_hi
                #pragma unroll
                for (int m2 = 0; m2 < 2; m2++)
                    ldm_x4(&a[m2 * 4], sAlo + (uint32_t)((mp * 2 + m2) * 16 * PITCH) * 2 + ko);
                #pragma unroll
                for (int m2 = 0; m2 < 2; m2++)
                    #pragma unroll
                    for (int nt = 0; nt < 4; nt++)
                        mma_bf16(acc[mp * 2 + m2][nt], &a[m2 * 4], &bhi[nt * 2]);
            }
        }
        __syncthreads();

        if (has_next) {
            char* stgN = smem + ((it + 1) & 1) * STAGE_SMEM;
            uint32_t hi[8], lo[8];
            split8(&av[0], &hi[0], &lo[0]);
            split8(&av[8], &hi[4], &lo[4]);
            *reinterpret_cast<uint4*>(stgN + 0 * TILE_SMEM + aSts)      = *reinterpret_cast<uint4*>(&hi[0]);
            *reinterpret_cast<uint4*>(stgN + 0 * TILE_SMEM + aSts + 16) = *reinterpret_cast<uint4*>(&hi[4]);
            *reinterpret_cast<uint4*>(stgN + 1 * TILE_SMEM + aSts)      = *reinterpret_cast<uint4*>(&lo[0]);
            *reinterpret_cast<uint4*>(stgN + 1 * TILE_SMEM + aSts + 16) = *reinterpret_cast<uint4*>(&lo[4]);
        }
    }

    // ---- epilogue: direct stores, C frag layout of m16n8
    const int g = lane >> 2;
    const int c = lane & 3;
    #pragma unroll
    for (int mt = 0; mt < 4; mt++) {
        const int row0 = by * BM + wm * 64 + mt * 16 + g;
        #pragma unroll
        for (int nt = 0; nt < 4; nt++) {
            const int col = i0 + wn * 32 + nt * 8 + c * 2;
            float* p0 = C + (size_t)row0 * E_DIM + col;
            float* p1 = C + (size_t)(row0 + 8) * E_DIM + col;
            *reinterpret_cast<float2*>(p0) = make_float2(acc[mt][nt][0], acc[mt][nt][1]);
            *reinterpret_cast<float2*>(p1) = make_float2(acc[mt][nt][2], acc[mt][nt][3]);
        }
    }
}

// ---------------- kernel 3: bias + L2 normalize ------------------------------
__global__ void bias_normalize_kernel(float* __restrict__ C, const float* __restrict__ b) {
    const int row = blockIdx.x;
    float* Cp = C + (size_t)row * E_DIM;
    const int t = threadIdx.x;  // 0..127

    float4 v  = reinterpret_cast<float4*>(Cp)[t];
    float4 bb = reinterpret_cast<const float4*>(b)[t];
    v.x += bb.x; v.y += bb.y; v.z += bb.z; v.w += bb.w;

    float ss = v.x * v.x + v.y * v.y + v.z * v.z + v.w * v.w;
    #pragma unroll
    for (int o = 16; o > 0; o >>= 1) ss += __shfl_xor_sync(0xffffffff, ss, o);

    __shared__ float warpsum[4];
    if ((t & 31) == 0) warpsum[t >> 5] = ss;
    __syncthreads();
    const float tot = warpsum[0] + warpsum[1] + warpsum[2] + warpsum[3];
    const float scale = 1.0f / fmaxf(sqrtf(tot), 1e-12f);

    v.x *= scale; v.y *= scale; v.z *= scale; v.w *= scale;
    reinterpret_cast<float4*>(Cp)[t] = v;
}

// -----------------------------------------------------------------------------
extern "C" void kernel_launch(void* const* d_in, const int* in_sizes, int n_in,
                              void* d_out, int out_size) {
    const float* x = (const float*)d_in[0];   // (16384, 2048)
    const float* w = (const float*)d_in[1];   // (512, 1537)
    const float* b = (const float*)d_in[2];   // (512,)
    float* out = (float*)d_out;               // (16384, 512)

    cudaFuncSetAttribute(mma_gemm_kernel,
                         cudaFuncAttributeMaxDynamicSharedMemorySize, SMEM_BYTES);

    build_band_kernel<<<E_DIM, 256>>>(w);

    dim3 grid(E_DIM / BN, N_ROWS / BM);       // (4, 128)
    mma_gemm_kernel<<<grid, THREADS, SMEM_BYTES>>>(x, out);

    bias_normalize_kernel<<<N_ROWS, 128>>>(out, b);
}

// round 7
// speedup vs baseline: 1.3395x; 1.3395x over previous
#include <cuda_runtime.h>
#include <cuda_fp16.h>
#include <cstdint>

// ConvEmbedding: out[n,i] = normalize_row( sum_k w[i,k]*x[n,i+k] + b[i] )
// C = X(16384x2048) @ W_band(512x2048)^T.
// R7: 2-term fp16 split: x = x_hi + x_lo (fp16 pair), w ~= fp16(w).
//     x_hi*w + x_lo*w, fp32 accum; fp16 products are exact -> err ~ 1.4e-4.

#define N_ROWS 16384
#define D_DIM  2048
#define E_DIM  512
#define K_DIM  1537

#define BM 128
#define BN 128
#define BK 32
#define PITCH 40                 // fp16 elems per smem row (80 B)
#define NITER 52                 // 1664 / 32, uniform for every E tile
#define THREADS 256

#define TILE_SMEM (BM * PITCH * 2)           // 10240 B per tile
#define STAGE_SMEM (3 * TILE_SMEM)           // Ahi, Alo, B = 30720 B
#define SMEM_BYTES (2 * STAGE_SMEM)          // double buffered = 61440 B

// ---------------- scratch (device globals) ----------------------------------
__device__ __half g_Wh[(size_t)E_DIM * D_DIM];

// ---------------- kernel 1: build banded W (fp16) ----------------------------
__global__ void build_band_kernel(const float* __restrict__ w) {
    const int i = blockIdx.x;  // 0..511
    const float* wrow = w + (size_t)i * K_DIM;
    for (int c = threadIdx.x; c < D_DIM; c += blockDim.x) {
        const int k = c - i;
        const float val = (k >= 0 && k < K_DIM) ? wrow[k] : 0.0f;
        g_Wh[(size_t)i * D_DIM + c] = __float2half_rn(val);
    }
}

// ---------------- mma helpers ------------------------------------------------
__device__ __forceinline__ void ldm_x4(uint32_t* r, uint32_t saddr) {
    asm volatile("ldmatrix.sync.aligned.m8n8.x4.shared.b16 {%0,%1,%2,%3}, [%4];"
                 : "=r"(r[0]), "=r"(r[1]), "=r"(r[2]), "=r"(r[3]) : "r"(saddr));
}
__device__ __forceinline__ void mma_f16(float* d, const uint32_t* a, const uint32_t* b) {
    asm volatile(
        "mma.sync.aligned.m16n8k16.row.col.f32.f16.f16.f32 "
        "{%0,%1,%2,%3}, {%4,%5,%6,%7}, {%8,%9}, {%0,%1,%2,%3};"
        : "+f"(d[0]), "+f"(d[1]), "+f"(d[2]), "+f"(d[3])
        : "r"(a[0]), "r"(a[1]), "r"(a[2]), "r"(a[3]), "r"(b[0]), "r"(b[1]));
}
__device__ __forceinline__ void cp_async16(uint32_t saddr, const void* gaddr) {
    asm volatile("cp.async.cg.shared.global [%0], [%1], 16;" :: "r"(saddr), "l"(gaddr));
}

// Convert 8 fp32 -> packed fp16 hi (4 u32) and lo (4 u32)
__device__ __forceinline__ void split8h(const float* v, uint32_t* hi, uint32_t* lo) {
    #pragma unroll
    for (int j = 0; j < 4; j++) {
        const float a = v[j * 2], b = v[j * 2 + 1];
        const __half2 h = __float22half2_rn(make_float2(a, b));
        const float ra = a - __half2float(__low2half(h));
        const float rb = b - __half2float(__high2half(h));
        const __half2 l = __float22half2_rn(make_float2(ra, rb));
        hi[j] = *reinterpret_cast<const uint32_t*>(&h);
        lo[j] = *reinterpret_cast<const uint32_t*>(&l);
    }
}

// ---------------- kernel 2: 2-term fp16 GEMM ---------------------------------
// Warp layout: 2 warps along M (tile 64) x 4 warps along N (tile 32).
// A loaded as fp32 LDG (one stage ahead), split to fp16 hi/lo in regs, STS'd.
// W loaded via cp.async (single fp16 array). Per k16: 10 LDSM.x4, 32 MMAs.
__global__ __launch_bounds__(THREADS, 2)
void mma_gemm_kernel(const float* __restrict__ X, float* __restrict__ C) {
    extern __shared__ __align__(128) char smem[];
    const uint32_t sb = (uint32_t)__cvta_generic_to_shared(smem);

    const int tid  = threadIdx.x;
    const int lane = tid & 31;
    const int wid  = tid >> 5;
    const int wm   = wid & 1;          // 2 warps along M: rows wm*64
    const int wn   = wid >> 1;         // 4 warps along N: cols wn*32
    const int bx = blockIdx.x;         // E tile (0..3)
    const int by = blockIdx.y;         // batch tile (0..127)
    const int i0 = bx * BN;
    const int kStart = i0;

    // ---- A loader: thread handles row tid>>1, 16 consecutive cols
    const int arow = tid >> 1;
    const int acol = (tid & 1) * 16;
    const float* Ap = X + (size_t)(by * BM + arow) * D_DIM + acol;
    const uint32_t aSts = (uint32_t)(arow * PITCH + acol) * 2;  // byte off in tile

    // ---- B loader (cp.async): tile slot 2, 2 chunks/thread
    const __half* Bsrc = g_Wh + (size_t)i0 * D_DIM;
    int brow[2], bcol[2];
    #pragma unroll
    for (int i = 0; i < 2; i++) {
        const int v = (i << 8) + tid;   // 0..511 within tile
        brow[i] = v >> 2;
        bcol[i] = (v & 3) * 8;
    }

    // fragment smem offsets (bytes, lane-dependent), relative to tile base
    const uint32_t aoff = ((uint32_t)((wm * 64 + (lane & 15)) * PITCH + (lane >> 4) * 8)) * 2;
    const uint32_t boff = ((uint32_t)((wn * 32 + (lane >> 4) * 8 + (lane & 7)) * PITCH
                                      + ((lane >> 3) & 1) * 8)) * 2;

    float acc[4][4][4];
    #pragma unroll
    for (int mt = 0; mt < 4; mt++)
        #pragma unroll
        for (int nt = 0; nt < 4; nt++)
            #pragma unroll
            for (int q = 0; q < 4; q++) acc[mt][nt][q] = 0.0f;

    float av[16];   // fp32 A prefetch (one stage ahead)

    // ---- prologue: stage 0
    {
        const int k0 = kStart;
        #pragma unroll
        for (int i = 0; i < 2; i++)
            cp_async16(sb + 2 * TILE_SMEM + (brow[i] * PITCH + bcol[i]) * 2,
                       Bsrc + (size_t)brow[i] * D_DIM + k0 + bcol[i]);
        asm volatile("cp.async.commit_group;" ::: "memory");

        #pragma unroll
        for (int q = 0; q < 4; q++)
            *reinterpret_cast<float4*>(&av[q * 4]) =
                *reinterpret_cast<const float4*>(Ap + k0 + q * 4);
        uint32_t hi[8], lo[8];
        split8h(&av[0], &hi[0], &lo[0]);
        split8h(&av[8], &hi[4], &lo[4]);
        *reinterpret_cast<uint4*>(smem + 0 * TILE_SMEM + aSts)      = *reinterpret_cast<uint4*>(&hi[0]);
        *reinterpret_cast<uint4*>(smem + 0 * TILE_SMEM + aSts + 16) = *reinterpret_cast<uint4*>(&hi[4]);
        *reinterpret_cast<uint4*>(smem + 1 * TILE_SMEM + aSts)      = *reinterpret_cast<uint4*>(&lo[0]);
        *reinterpret_cast<uint4*>(smem + 1 * TILE_SMEM + aSts + 16) = *reinterpret_cast<uint4*>(&lo[4]);
    }

    for (int it = 0; it < NITER; it++) {
        const int has_next = (it + 1 < NITER);
        if (has_next) {
            const int k0 = kStart + (it + 1) * BK;
            const uint32_t stg = sb + ((it + 1) & 1) * STAGE_SMEM;
            #pragma unroll
            for (int i = 0; i < 2; i++)
                cp_async16(stg + 2 * TILE_SMEM + (brow[i] * PITCH + bcol[i]) * 2,
                           Bsrc + (size_t)brow[i] * D_DIM + k0 + bcol[i]);
            asm volatile("cp.async.commit_group;" ::: "memory");
            #pragma unroll
            for (int q = 0; q < 4; q++)
                *reinterpret_cast<float4*>(&av[q * 4]) =
                    *reinterpret_cast<const float4*>(Ap + k0 + q * 4);
            asm volatile("cp.async.wait_group 1;" ::: "memory");
        } else {
            asm volatile("cp.async.wait_group 0;" ::: "memory");
        }
        __syncthreads();

        const uint32_t stg = sb + (it & 1) * STAGE_SMEM;
        const uint32_t sAhi = stg + 0 * TILE_SMEM + aoff;
        const uint32_t sAlo = stg + 1 * TILE_SMEM + aoff;
        const uint32_t sB   = stg + 2 * TILE_SMEM + boff;

        #pragma unroll
        for (int k16 = 0; k16 < BK; k16 += 16) {
            const uint32_t ko = k16 * 2;  // byte offset in row
            uint32_t bfr[8];

            #pragma unroll
            for (int bt = 0; bt < 2; bt++)
                ldm_x4(&bfr[bt * 4], sB + (uint32_t)(bt * 16 * PITCH) * 2 + ko);

            // process m-tiles in pairs: A fragments live in 8 regs only
            #pragma unroll
            for (int mp = 0; mp < 2; mp++) {
                uint32_t a[8];
                #pragma unroll
                for (int m2 = 0; m2 < 2; m2++)
                    ldm_x4(&a[m2 * 4], sAhi + (uint32_t)((mp * 2 + m2) * 16 * PITCH) * 2 + ko);
                // term 1: a_hi * b
                #pragma unroll
                for (int m2 = 0; m2 < 2; m2++)
                    #pragma unroll
                    for (int nt = 0; nt < 4; nt++)
                        mma_f16(acc[mp * 2 + m2][nt], &a[m2 * 4], &bfr[nt * 2]);
                // term 2: a_lo * b
                #pragma unroll
                for (int m2 = 0; m2 < 2; m2++)
                    ldm_x4(&a[m2 * 4], sAlo + (uint32_t)((mp * 2 + m2) * 16 * PITCH) * 2 + ko);
                #pragma unroll
                for (int m2 = 0; m2 < 2; m2++)
                    #pragma unroll
                    for (int nt = 0; nt < 4; nt++)
                        mma_f16(acc[mp * 2 + m2][nt], &a[m2 * 4], &bfr[nt * 2]);
            }
        }
        __syncthreads();

        if (has_next) {
            char* stgN = smem + ((it + 1) & 1) * STAGE_SMEM;
            uint32_t hi[8], lo[8];
            split8h(&av[0], &hi[0], &lo[0]);
            split8h(&av[8], &hi[4], &lo[4]);
            *reinterpret_cast<uint4*>(stgN + 0 * TILE_SMEM + aSts)      = *reinterpret_cast<uint4*>(&hi[0]);
            *reinterpret_cast<uint4*>(stgN + 0 * TILE_SMEM + aSts + 16) = *reinterpret_cast<uint4*>(&hi[4]);
            *reinterpret_cast<uint4*>(stgN + 1 * TILE_SMEM + aSts)      = *reinterpret_cast<uint4*>(&lo[0]);
            *reinterpret_cast<uint4*>(stgN + 1 * TILE_SMEM + aSts + 16) = *reinterpret_cast<uint4*>(&lo[4]);
        }
    }

    // ---- epilogue: direct stores, C frag layout of m16n8
    const int g = lane >> 2;
    const int c = lane & 3;
    #pragma unroll
    for (int mt = 0; mt < 4; mt++) {
        const int row0 = by * BM + wm * 64 + mt * 16 + g;
        #pragma unroll
        for (int nt = 0; nt < 4; nt++) {
            const int col = i0 + wn * 32 + nt * 8 + c * 2;
            float* p0 = C + (size_t)row0 * E_DIM + col;
            float* p1 = C + (size_t)(row0 + 8) * E_DIM + col;
            *reinterpret_cast<float2*>(p0) = make_float2(acc[mt][nt][0], acc[mt][nt][1]);
            *reinterpret_cast<float2*>(p1) = make_float2(acc[mt][nt][2], acc[mt][nt][3]);
        }
    }
}

// ---------------- kernel 3: bias + L2 normalize ------------------------------
__global__ void bias_normalize_kernel(float* __restrict__ C, const float* __restrict__ b) {
    const int row = blockIdx.x;
    float* Cp = C + (size_t)row * E_DIM;
    const int t = threadIdx.x;  // 0..127

    float4 v  = reinterpret_cast<float4*>(Cp)[t];
    float4 bb = reinterpret_cast<const float4*>(b)[t];
    v.x += bb.x; v.y += bb.y; v.z += bb.z; v.w += bb.w;

    float ss = v.x * v.x + v.y * v.y + v.z * v.z + v.w * v.w;
    #pragma unroll
    for (int o = 16; o > 0; o >>= 1) ss += __shfl_xor_sync(0xffffffff, ss, o);

    __shared__ float warpsum[4];
    if ((t & 31) == 0) warpsum[t >> 5] = ss;
    __syncthreads();
    const float tot = warpsum[0] + warpsum[1] + warpsum[2] + warpsum[3];
    const float scale = 1.0f / fmaxf(sqrtf(tot), 1e-12f);

    v.x *= scale; v.y *= scale; v.z *= scale; v.w *= scale;
    reinterpret_cast<float4*>(Cp)[t] = v;
}

// -----------------------------------------------------------------------------
extern "C" void kernel_launch(void* const* d_in, const int* in_sizes, int n_in,
                              void* d_out, int out_size) {
    const float* x = (const float*)d_in[0];   // (16384, 2048)
    const float* w = (const float*)d_in[1];   // (512, 1537)
    const float* b = (const float*)d_in[2];   // (512,)
    float* out = (float*)d_out;               // (16384, 512)

    cudaFuncSetAttribute(mma_gemm_kernel,
                         cudaFuncAttributeMaxDynamicSharedMemorySize, SMEM_BYTES);

    build_band_kernel<<<E_DIM, 256>>>(w);

    dim3 grid(E_DIM / BN, N_ROWS / BM);       // (4, 128)
    mma_gemm_kernel<<<grid, THREADS, SMEM_BYTES>>>(x, out);

    bias_normalize_kernel<<<N_ROWS, 128>>>(out, b);
}

// round 8
// speedup vs baseline: 1.8855x; 1.4076x over previous
#include <cuda_runtime.h>
#include <cuda_fp16.h>
#include <cstdint>

// ConvEmbedding: out[n,i] = normalize_row( sum_k w[i,k]*x[n,i+k] + b[i] )
// C = X(16384x2048) @ W_band(512x2048)^T.
// R8: plain fp16 GEMM (x and w both rounded to fp16), fp32 accumulation.
//     Error ~ sqrt(2) * u_fp16/sqrt(3) ~ 2.9e-4 << 1e-3 gate.

#define N_ROWS 16384
#define D_DIM  2048
#define E_DIM  512
#define K_DIM  1537

#define BM 128
#define BN 128
#define BK 32
#define PITCH 40                 // fp16 elems per smem row (80 B)
#define NITER 52                 // 1664 / 32, uniform for every E tile
#define THREADS 256

#define TILE_SMEM (BM * PITCH * 2)           // 10240 B per tile
#define STAGE_SMEM (2 * TILE_SMEM)           // A, B = 20480 B
#define SMEM_BYTES (2 * STAGE_SMEM)          // double buffered = 40960 B

// ---------------- scratch (device globals) ----------------------------------
__device__ __half g_Wh[(size_t)E_DIM * D_DIM];

// ---------------- kernel 1: build banded W (fp16) ----------------------------
__global__ void build_band_kernel(const float* __restrict__ w) {
    const int i = blockIdx.x;  // 0..511
    const float* wrow = w + (size_t)i * K_DIM;
    for (int c = threadIdx.x; c < D_DIM; c += blockDim.x) {
        const int k = c - i;
        const float val = (k >= 0 && k < K_DIM) ? wrow[k] : 0.0f;
        g_Wh[(size_t)i * D_DIM + c] = __float2half_rn(val);
    }
}

// ---------------- mma helpers ------------------------------------------------
__device__ __forceinline__ void ldm_x4(uint32_t* r, uint32_t saddr) {
    asm volatile("ldmatrix.sync.aligned.m8n8.x4.shared.b16 {%0,%1,%2,%3}, [%4];"
                 : "=r"(r[0]), "=r"(r[1]), "=r"(r[2]), "=r"(r[3]) : "r"(saddr));
}
__device__ __forceinline__ void mma_f16(float* d, const uint32_t* a, const uint32_t* b) {
    asm volatile(
        "mma.sync.aligned.m16n8k16.row.col.f32.f16.f16.f32 "
        "{%0,%1,%2,%3}, {%4,%5,%6,%7}, {%8,%9}, {%0,%1,%2,%3};"
        : "+f"(d[0]), "+f"(d[1]), "+f"(d[2]), "+f"(d[3])
        : "r"(a[0]), "r"(a[1]), "r"(a[2]), "r"(a[3]), "r"(b[0]), "r"(b[1]));
}
__device__ __forceinline__ void cp_async16(uint32_t saddr, const void* gaddr) {
    asm volatile("cp.async.cg.shared.global [%0], [%1], 16;" :: "r"(saddr), "l"(gaddr));
}

// Convert 8 fp32 -> 4 packed fp16x2
__device__ __forceinline__ void cvt8h(const float* v, uint32_t* h) {
    #pragma unroll
    for (int j = 0; j < 4; j++) {
        const __half2 p = __float22half2_rn(make_float2(v[j * 2], v[j * 2 + 1]));
        h[j] = *reinterpret_cast<const uint32_t*>(&p);
    }
}

// ---------------- kernel 2: fp16 GEMM ----------------------------------------
// Warp layout: 2 warps along M (tile 64) x 4 warps along N (tile 32).
// A loaded as fp32 LDG (one stage ahead), converted to fp16 in regs, STS'd.
// W loaded via cp.async. Per k16: 6 LDSM.x4, 16 MMAs.
__global__ __launch_bounds__(THREADS, 2)
void mma_gemm_kernel(const float* __restrict__ X, float* __restrict__ C) {
    extern __shared__ __align__(128) char smem[];
    const uint32_t sb = (uint32_t)__cvta_generic_to_shared(smem);

    const int tid  = threadIdx.x;
    const int lane = tid & 31;
    const int wid  = tid >> 5;
    const int wm   = wid & 1;          // 2 warps along M: rows wm*64
    const int wn   = wid >> 1;         // 4 warps along N: cols wn*32
    const int bx = blockIdx.x;         // E tile (0..3)
    const int by = blockIdx.y;         // batch tile (0..127)
    const int i0 = bx * BN;
    const int kStart = i0;

    // ---- A loader: thread handles row tid>>1, 16 consecutive cols
    const int arow = tid >> 1;
    const int acol = (tid & 1) * 16;
    const float* Ap = X + (size_t)(by * BM + arow) * D_DIM + acol;
    const uint32_t aSts = (uint32_t)(arow * PITCH + acol) * 2;  // byte off in tile

    // ---- B loader (cp.async): tile slot 1, 2 chunks/thread
    const __half* Bsrc = g_Wh + (size_t)i0 * D_DIM;
    int brow[2], bcol[2];
    #pragma unroll
    for (int i = 0; i < 2; i++) {
        const int v = (i << 8) + tid;   // 0..511 within tile
        brow[i] = v >> 2;
        bcol[i] = (v & 3) * 8;
    }

    // fragment smem offsets (bytes, lane-dependent), relative to tile base
    const uint32_t aoff = ((uint32_t)((wm * 64 + (lane & 15)) * PITCH + (lane >> 4) * 8)) * 2;
    const uint32_t boff = ((uint32_t)((wn * 32 + (lane >> 4) * 8 + (lane & 7)) * PITCH
                                      + ((lane >> 3) & 1) * 8)) * 2;

    float acc[4][4][4];
    #pragma unroll
    for (int mt = 0; mt < 4; mt++)
        #pragma unroll
        for (int nt = 0; nt < 4; nt++)
            #pragma unroll
            for (int q = 0; q < 4; q++) acc[mt][nt][q] = 0.0f;

    float av[16];   // fp32 A prefetch (one stage ahead)

    // ---- prologue: stage 0
    {
        const int k0 = kStart;
        #pragma unroll
        for (int i = 0; i < 2; i++)
            cp_async16(sb + 1 * TILE_SMEM + (brow[i] * PITCH + bcol[i]) * 2,
                       Bsrc + (size_t)brow[i] * D_DIM + k0 + bcol[i]);
        asm volatile("cp.async.commit_group;" ::: "memory");

        #pragma unroll
        for (int q = 0; q < 4; q++)
            *reinterpret_cast<float4*>(&av[q * 4]) =
                *reinterpret_cast<const float4*>(Ap + k0 + q * 4);
        uint32_t h[8];
        cvt8h(&av[0], &h[0]);
        cvt8h(&av[8], &h[4]);
        *reinterpret_cast<uint4*>(smem + aSts)      = *reinterpret_cast<uint4*>(&h[0]);
        *reinterpret_cast<uint4*>(smem + aSts + 16) = *reinterpret_cast<uint4*>(&h[4]);
    }

    for (int it = 0; it < NITER; it++) {
        const int has_next = (it + 1 < NITER);
        if (has_next) {
            const int k0 = kStart + (it + 1) * BK;
            const uint32_t stg = sb + ((it + 1) & 1) * STAGE_SMEM;
            #pragma unroll
            for (int i = 0; i < 2; i++)
                cp_async16(stg + 1 * TILE_SMEM + (brow[i] * PITCH + bcol[i]) * 2,
                           Bsrc + (size_t)brow[i] * D_DIM + k0 + bcol[i]);
            asm volatile("cp.async.commit_group;" ::: "memory");
            #pragma unroll
            for (int q = 0; q < 4; q++)
                *reinterpret_cast<float4*>(&av[q * 4]) =
                    *reinterpret_cast<const float4*>(Ap + k0 + q * 4);
            asm volatile("cp.async.wait_group 1;" ::: "memory");
        } else {
            asm volatile("cp.async.wait_group 0;" ::: "memory");
        }
        __syncthreads();

        const uint32_t stg = sb + (it & 1) * STAGE_SMEM;
        const uint32_t sA = stg + 0 * TILE_SMEM + aoff;
        const uint32_t sB = stg + 1 * TILE_SMEM + boff;

        #pragma unroll
        for (int k16 = 0; k16 < BK; k16 += 16) {
            const uint32_t ko = k16 * 2;  // byte offset in row
            uint32_t bfr[8];
            #pragma unroll
            for (int bt = 0; bt < 2; bt++)
                ldm_x4(&bfr[bt * 4], sB + (uint32_t)(bt * 16 * PITCH) * 2 + ko);

            #pragma unroll
            for (int mp = 0; mp < 2; mp++) {
                uint32_t a[8];
                #pragma unroll
                for (int m2 = 0; m2 < 2; m2++)
                    ldm_x4(&a[m2 * 4], sA + (uint32_t)((mp * 2 + m2) * 16 * PITCH) * 2 + ko);
                #pragma unroll
                for (int m2 = 0; m2 < 2; m2++)
                    #pragma unroll
                    for (int nt = 0; nt < 4; nt++)
                        mma_f16(acc[mp * 2 + m2][nt], &a[m2 * 4], &bfr[nt * 2]);
            }
        }
        __syncthreads();

        if (has_next) {
            char* stgN = smem + ((it + 1) & 1) * STAGE_SMEM;
            uint32_t h[8];
            cvt8h(&av[0], &h[0]);
            cvt8h(&av[8], &h[4]);
            *reinterpret_cast<uint4*>(stgN + aSts)      = *reinterpret_cast<uint4*>(&h[0]);
            *reinterpret_cast<uint4*>(stgN + aSts + 16) = *reinterpret_cast<uint4*>(&h[4]);
        }
    }

    // ---- epilogue: direct stores, C frag layout of m16n8
    const int g = lane >> 2;
    const int c = lane & 3;
    #pragma unroll
    for (int mt = 0; mt < 4; mt++) {
        const int row0 = by * BM + wm * 64 + mt * 16 + g;
        #pragma unroll
        for (int nt = 0; nt < 4; nt++) {
            const int col = i0 + wn * 32 + nt * 8 + c * 2;
            float* p0 = C + (size_t)row0 * E_DIM + col;
            float* p1 = C + (size_t)(row0 + 8) * E_DIM + col;
            *reinterpret_cast<float2*>(p0) = make_float2(acc[mt][nt][0], acc[mt][nt][1]);
            *reinterpret_cast<float2*>(p1) = make_float2(acc[mt][nt][2], acc[mt][nt][3]);
        }
    }
}

// ---------------- kernel 3: bias + L2 normalize ------------------------------
__global__ void bias_normalize_kernel(float* __restrict__ C, const float* __restrict__ b) {
    const int row = blockIdx.x;
    float* Cp = C + (size_t)row * E_DIM;
    const int t = threadIdx.x;  // 0..127

    float4 v  = reinterpret_cast<float4*>(Cp)[t];
    float4 bb = reinterpret_cast<const float4*>(b)[t];
    v.x += bb.x; v.y += bb.y; v.z += bb.z; v.w += bb.w;

    float ss = v.x * v.x + v.y * v.y + v.z * v.z + v.w * v.w;
    #pragma unroll
    for (int o = 16; o > 0; o >>= 1) ss += __shfl_xor_sync(0xffffffff, ss, o);

    __shared__ float warpsum[4];
    if ((t & 31) == 0) warpsum[t >> 5] = ss;
    __syncthreads();
    const float tot = warpsum[0] + warpsum[1] + warpsum[2] + warpsum[3];
    const float scale = 1.0f / fmaxf(sqrtf(tot), 1e-12f);

    v.x *= scale; v.y *= scale; v.z *= scale; v.w *= scale;
    reinterpret_cast<float4*>(Cp)[t] = v;
}

// -----------------------------------------------------------------------------
extern "C" void kernel_launch(void* const* d_in, const int* in_sizes, int n_in,
                              void* d_out, int out_size) {
    const float* x = (const float*)d_in[0];   // (16384, 2048)
    const float* w = (const float*)d_in[1];   // (512, 1537)
    const float* b = (const float*)d_in[2];   // (512,)
    float* out = (float*)d_out;               // (16384, 512)

    cudaFuncSetAttribute(mma_gemm_kernel,
                         cudaFuncAttributeMaxDynamicSharedMemorySize, SMEM_BYTES);

    build_band_kernel<<<E_DIM, 256>>>(w);

    dim3 grid(E_DIM / BN, N_ROWS / BM);       // (4, 128)
    mma_gemm_kernel<<<grid, THREADS, SMEM_BYTES>>>(x, out);

    bias_normalize_kernel<<<N_ROWS, 128>>>(out, b);
}

// round 9
// speedup vs baseline: 2.1128x; 1.1206x over previous
#include <cuda_runtime.h>
#include <cuda_fp16.h>
#include <cstdint>

// ConvEmbedding: out[n,i] = normalize_row( sum_k w[i,k]*x[n,i+k] + b[i] )
// C = X(16384x2048) @ W_band(512x2048)^T, fp16 inputs, fp32 accumulation.
// R9: X pre-converted to fp16; GEMM pure cp.async, BK=64, 3-stage, 1 sync/iter.

#define N_ROWS 16384
#define D_DIM  2048
#define E_DIM  512
#define K_DIM  1537

#define BM 128
#define BN 128
#define BK 64
#define PITCH 72                 // fp16 elems per smem row (144 B)
#define NITER 26                 // 1664 / 64, uniform for every E tile
#define THREADS 256
#define STAGES 3

#define TILE_SMEM (BM * PITCH * 2)           // 18432 B per tile
#define STAGE_SMEM (2 * TILE_SMEM)           // A, B = 36864 B
#define SMEM_BYTES (STAGES * STAGE_SMEM)     // 110592 B

// ---------------- scratch (device globals) ----------------------------------
__device__ __half g_Xh[(size_t)N_ROWS * D_DIM];
__device__ __half g_Wh[(size_t)E_DIM * D_DIM];

// ---------------- kernel 1: convert X to fp16 --------------------------------
__global__ __launch_bounds__(256)
void convert_x_kernel(const float* __restrict__ x) {
    size_t i = ((size_t)blockIdx.x * 256 + threadIdx.x) * 8;
    float4 a = *reinterpret_cast<const float4*>(x + i);
    float4 c = *reinterpret_cast<const float4*>(x + i + 4);
    __half2 h[4];
    h[0] = __float22half2_rn(make_float2(a.x, a.y));
    h[1] = __float22half2_rn(make_float2(a.z, a.w));
    h[2] = __float22half2_rn(make_float2(c.x, c.y));
    h[3] = __float22half2_rn(make_float2(c.z, c.w));
    *reinterpret_cast<uint4*>(&g_Xh[i]) = *reinterpret_cast<uint4*>(h);
}

// ---------------- kernel 2: build banded W (fp16) ----------------------------
__global__ void build_band_kernel(const float* __restrict__ w) {
    const int i = blockIdx.x;  // 0..511
    const float* wrow = w + (size_t)i * K_DIM;
    for (int c = threadIdx.x; c < D_DIM; c += blockDim.x) {
        const int k = c - i;
        const float val = (k >= 0 && k < K_DIM) ? wrow[k] : 0.0f;
        g_Wh[(size_t)i * D_DIM + c] = __float2half_rn(val);
    }
}

// ---------------- mma helpers ------------------------------------------------
__device__ __forceinline__ void ldm_x4(uint32_t* r, uint32_t saddr) {
    asm volatile("ldmatrix.sync.aligned.m8n8.x4.shared.b16 {%0,%1,%2,%3}, [%4];"
                 : "=r"(r[0]), "=r"(r[1]), "=r"(r[2]), "=r"(r[3]) : "r"(saddr));
}
__device__ __forceinline__ void mma_f16(float* d, const uint32_t* a, const uint32_t* b) {
    asm volatile(
        "mma.sync.aligned.m16n8k16.row.col.f32.f16.f16.f32 "
        "{%0,%1,%2,%3}, {%4,%5,%6,%7}, {%8,%9}, {%0,%1,%2,%3};"
        : "+f"(d[0]), "+f"(d[1]), "+f"(d[2]), "+f"(d[3])
        : "r"(a[0]), "r"(a[1]), "r"(a[2]), "r"(a[3]), "r"(b[0]), "r"(b[1]));
}
__device__ __forceinline__ void cp_async16(uint32_t saddr, const void* gaddr) {
    asm volatile("cp.async.cg.shared.global [%0], [%1], 16;" :: "r"(saddr), "l"(gaddr));
}

// ---------------- kernel 3: fp16 GEMM -----------------------------------------
// Warp layout: 2 warps along M (tile 64) x 4 warps along N (tile 32).
// 3-stage cp.async pipeline, BK=64, single __syncthreads per iteration.
__global__ __launch_bounds__(THREADS, 2)
void mma_gemm_kernel(float* __restrict__ C) {
    extern __shared__ __align__(128) char smem[];
    const uint32_t sb = (uint32_t)__cvta_generic_to_shared(smem);

    const int tid  = threadIdx.x;
    const int lane = tid & 31;
    const int wid  = tid >> 5;
    const int wm   = wid & 1;          // 2 warps along M
    const int wn   = wid >> 1;         // 4 warps along N
    const int bx = blockIdx.x;         // E tile (0..3)
    const int by = blockIdx.y;         // batch tile (0..127)
    const int i0 = bx * BN;
    const int kStart = i0;

    // ---- loaders: tile = 128 rows x 64 fp16 (128 B/row data, 144 B pitch)
    // 1024 chunks of 16 B per tile; 4 chunks/thread per tile.
    const __half* Asrc = g_Xh + (size_t)by * BM * D_DIM;
    const __half* Bsrc = g_Wh + (size_t)i0 * D_DIM;
    int lrow[4], lchk[4];
    #pragma unroll
    for (int i = 0; i < 4; i++) {
        const int v = tid + i * THREADS;   // 0..1023
        lrow[i] = v >> 3;
        lchk[i] = v & 7;
    }

    // fragment smem offsets (bytes), relative to tile base
    const uint32_t aoff = ((uint32_t)((wm * 64 + (lane & 15)) * PITCH + (lane >> 4) * 8)) * 2;
    const uint32_t boff = ((uint32_t)((wn * 32 + (lane >> 4) * 8 + (lane & 7)) * PITCH
                                      + ((lane >> 3) & 1) * 8)) * 2;

    float acc[4][4][4];
    #pragma unroll
    for (int mt = 0; mt < 4; mt++)
        #pragma unroll
        for (int nt = 0; nt < 4; nt++)
            #pragma unroll
            for (int q = 0; q < 4; q++) acc[mt][nt][q] = 0.0f;

    // stage loader
    auto load_stage = [&](int s, int k0) {
        const uint32_t stg = sb + (uint32_t)s * STAGE_SMEM;
        #pragma unroll
        for (int i = 0; i < 4; i++) {
            const uint32_t so = (uint32_t)(lrow[i] * PITCH * 2 + lchk[i] * 16);
            cp_async16(stg + so,
                       Asrc + (size_t)lrow[i] * D_DIM + k0 + lchk[i] * 8);
            cp_async16(stg + TILE_SMEM + so,
                       Bsrc + (size_t)lrow[i] * D_DIM + k0 + lchk[i] * 8);
        }
        asm volatile("cp.async.commit_group;" ::: "memory");
    };

    // ---- prologue: stages 0, 1
    load_stage(0, kStart);
    load_stage(1, kStart + BK);
    asm volatile("cp.async.wait_group 1;" ::: "memory");
    __syncthreads();

    for (int it = 0; it < NITER; it++) {
        // issue stage it+2 (overwrites stage consumed at it-1; safe: trailing
        // __syncthreads of iteration it-1 released it)
        if (it + 2 < NITER)
            load_stage((it + 2) % STAGES, kStart + (it + 2) * BK);

        const uint32_t stg = sb + (uint32_t)(it % STAGES) * STAGE_SMEM;
        const uint32_t sA = stg + aoff;
        const uint32_t sB = stg + TILE_SMEM + boff;

        #pragma unroll
        for (int k16 = 0; k16 < BK; k16 += 16) {
            const uint32_t ko = k16 * 2;  // byte offset in row
            uint32_t bfr[8];
            #pragma unroll
            for (int bt = 0; bt < 2; bt++)
                ldm_x4(&bfr[bt * 4], sB + (uint32_t)(bt * 16 * PITCH) * 2 + ko);

            #pragma unroll
            for (int mp = 0; mp < 2; mp++) {
                uint32_t a[8];
                #pragma unroll
                for (int m2 = 0; m2 < 2; m2++)
                    ldm_x4(&a[m2 * 4], sA + (uint32_t)((mp * 2 + m2) * 16 * PITCH) * 2 + ko);
                #pragma unroll
                for (int m2 = 0; m2 < 2; m2++)
                    #pragma unroll
                    for (int nt = 0; nt < 4; nt++)
                        mma_f16(acc[mp * 2 + m2][nt], &a[m2 * 4], &bfr[nt * 2]);
            }
        }

        // make stage it+1 ready, then release stage it for overwrite
        if (it + 2 < NITER) {
            asm volatile("cp.async.wait_group 1;" ::: "memory");
        } else if (it + 1 < NITER) {
            asm volatile("cp.async.wait_group 0;" ::: "memory");
        }
        __syncthreads();
    }

    // ---- epilogue: direct stores, C frag layout of m16n8
    const int g = lane >> 2;
    const int c = lane & 3;
    #pragma unroll
    for (int mt = 0; mt < 4; mt++) {
        const int row0 = by * BM + wm * 64 + mt * 16 + g;
        #pragma unroll
        for (int nt = 0; nt < 4; nt++) {
            const int col = i0 + wn * 32 + nt * 8 + c * 2;
            float* p0 = C + (size_t)row0 * E_DIM + col;
            float* p1 = C + (size_t)(row0 + 8) * E_DIM + col;
            *reinterpret_cast<float2*>(p0) = make_float2(acc[mt][nt][0], acc[mt][nt][1]);
            *reinterpret_cast<float2*>(p1) = make_float2(acc[mt][nt][2], acc[mt][nt][3]);
        }
    }
}

// ---------------- kernel 4: bias + L2 normalize ------------------------------
__global__ void bias_normalize_kernel(float* __restrict__ C, const float* __restrict__ b) {
    const int row = blockIdx.x;
    float* Cp = C + (size_t)row * E_DIM;
    const int t = threadIdx.x;  // 0..127

    float4 v  = reinterpret_cast<float4*>(Cp)[t];
    float4 bb = reinterpret_cast<const float4*>(b)[t];
    v.x += bb.x; v.y += bb.y; v.z += bb.z; v.w += bb.w;

    float ss = v.x * v.x + v.y * v.y + v.z * v.z + v.w * v.w;
    #pragma unroll
    for (int o = 16; o > 0; o >>= 1) ss += __shfl_xor_sync(0xffffffff, ss, o);

    __shared__ float warpsum[4];
    if ((t & 31) == 0) warpsum[t >> 5] = ss;
    __syncthreads();
    const float tot = warpsum[0] + warpsum[1] + warpsum[2] + warpsum[3];
    const float scale = 1.0f / fmaxf(sqrtf(tot), 1e-12f);

    v.x *= scale; v.y *= scale; v.z *= scale; v.w *= scale;
    reinterpret_cast<float4*>(Cp)[t] = v;
}

// -----------------------------------------------------------------------------
extern "C" void kernel_launch(void* const* d_in, const int* in_sizes, int n_in,
                              void* d_out, int out_size) {
    const float* x = (const float*)d_in[0];   // (16384, 2048)
    const float* w = (const float*)d_in[1];   // (512, 1537)
    const float* b = (const float*)d_in[2];   // (512,)
    float* out = (float*)d_out;               // (16384, 512)

    cudaFuncSetAttribute(mma_gemm_kernel,
                         cudaFuncAttributeMaxDynamicSharedMemorySize, SMEM_BYTES);

    convert_x_kernel<<<(N_ROWS * D_DIM) / (256 * 8), 256>>>(x);
    build_band_kernel<<<E_DIM, 256>>>(w);

    dim3 grid(E_DIM / BN, N_ROWS / BM);       // (4, 128)
    mma_gemm_kernel<<<grid, THREADS, SMEM_BYTES>>>(out);

    bias_normalize_kernel<<<N_ROWS, 128>>>(out, b);
}